// round 14
// baseline (speedup 1.0000x reference)
#include <cuda_runtime.h>
#include <cuda_bf16.h>

// ---- static problem config ----
#define NIMG 32
#define HH   1024
#define WW   1024
#define BHW  16                 // pool window
#define BSTR 14                 // block stride
#define BC   73                 // blocks per spatial dim
#define BC2  (BC*BC)            // 5329
#define NROW (NIMG*BC)          // 2336  (n, bh) row-blocks
#define NBLK (NROW*BC)          // 170528 total blocks
#define OUT_ELEMS (NBLK*3)      // 511584 floats = 127896 float4 (exact)
#define OUT_VEC4  (OUT_ELEMS/4)
#define THRESH 0.9f
#define W4     (WW/4)

// scratch (device globals — no allocation allowed)
__device__ unsigned g_bitmap[NROW * 3];   // 96-bit active mask per (n,bh) row
__device__ unsigned g_count[NROW];        // popcount per row

__device__ __forceinline__ float4 fmax4(float4 a, float4 b)
{
    return make_float4(fmaxf(a.x, b.x), fmaxf(a.y, b.y),
                       fmaxf(a.z, b.z), fmaxf(a.w, b.w));
}

// ---------------------------------------------------------------------------
// K1: pool — unchanged from R12/R13 (proven ~10.1us wall). One CTA per
// (n, bh), 128 threads (2 float4 columns each). MONOTONE EARLY EXIT:
// chunk 1 = 4 rows (8 front-batched loads, MLP=8) -> checkpoint; ~92% of
// CTAs see all 73 windows active and stop. Survivors read the remaining
// rows and re-run the checkpoint. Zero is the exact identity.
// ---------------------------------------------------------------------------
__global__ __launch_bounds__(128) void pool_kernel(const float* __restrict__ mask)
{
    const int cta = blockIdx.x;          // n*BC + bh
    const int n   = cta / BC;
    const int bh  = cta % BC;
    const int tid = threadIdx.x;

    __shared__ float4   sv4[256];        // 1024 column maxima
    __shared__ unsigned sbm[3];

    // padded window [bh*14, bh*14+16) -> unpadded rows [bh*14-1, bh*14+15)
    const int h0 = bh * BSTR - 1;
    const int hs = (h0 < 0) ? 0 : h0;
    const int he = (h0 + BHW < HH) ? (h0 + BHW) : HH;
    const int total_rows = he - hs;      // 15 (bh==0) or 16

    const float4* base = (const float4*)(mask + (size_t)n * HH * WW) + hs * W4;

    // ---- chunk 1: static 4 rows, 8 independent loads ----
    float4 a0, a1;
    {
        float4 x0 = base[0 * W4 + tid];
        float4 y0 = base[0 * W4 + 128 + tid];
        float4 x1 = base[1 * W4 + tid];
        float4 y1 = base[1 * W4 + 128 + tid];
        float4 x2 = base[2 * W4 + tid];
        float4 y2 = base[2 * W4 + 128 + tid];
        float4 x3 = base[3 * W4 + tid];
        float4 y3 = base[3 * W4 + 128 + tid];
        a0 = fmax4(fmax4(x0, x1), fmax4(x2, x3));
        a1 = fmax4(fmax4(y0, y1), fmax4(y2, y3));
    }

    // ---- checkpoint 1 ----
    sv4[tid]       = a0;
    sv4[tid + 128] = a1;
    __syncthreads();
    {
        const float* sv = (const float*)sv4;
        if (tid < 96) {                   // warps 0,1,2
            float m = 0.f;
            if (tid < BC) {
                const int w0 = tid * BSTR - 1;
                const int ws = (w0 < 0) ? 0 : w0;
                const int we = (w0 + BHW < WW) ? (w0 + BHW) : WW;
                for (int w = ws; w < we; ++w) m = fmaxf(m, sv[w]);
            }
            unsigned b = __ballot_sync(0xFFFFFFFFu, m > THRESH);
            if ((tid & 31) == 0) sbm[tid >> 5] = b;
        }
    }
    __syncthreads();

    const bool done1 = (sbm[0] == 0xFFFFFFFFu) &
                       (sbm[1] == 0xFFFFFFFFu) &
                       (sbm[2] == 0x1FFu);

    if (!done1) {
        // ---- chunk 2: all remaining rows, one pass ----
        #pragma unroll 4
        for (int h = 4; h < total_rows; ++h) {
            a0 = fmax4(a0, base[h * W4 + tid]);
            a1 = fmax4(a1, base[h * W4 + 128 + tid]);
        }

        sv4[tid]       = a0;
        sv4[tid + 128] = a1;
        __syncthreads();
        const float* sv = (const float*)sv4;
        if (tid < 96) {
            float m = 0.f;
            if (tid < BC) {
                const int w0 = tid * BSTR - 1;
                const int ws = (w0 < 0) ? 0 : w0;
                const int we = (w0 + BHW < WW) ? (w0 + BHW) : WW;
                for (int w = ws; w < we; ++w) m = fmaxf(m, sv[w]);
            }
            unsigned b = __ballot_sync(0xFFFFFFFFu, m > THRESH);
            if ((tid & 31) == 0) sbm[tid >> 5] = b;
        }
        __syncthreads();
    }

    if (tid < 3) g_bitmap[cta * 3 + tid] = sbm[tid];
    if (tid == 0)
        g_count[cta] = (unsigned)(__popc(sbm[0]) + __popc(sbm[1]) + __popc(sbm[2]));
}

// ---------------------------------------------------------------------------
// K2: write with PDL overlap. Launched with programmatic stream
// serialization: starts while pool is still running.
//   Phase 0 (pool-INDEPENDENT, overlaps pool): speculative dense stores —
//            the dense output is a pure function of the slot index.
//   cudaGridDependencySynchronize(): wait for pool's memory.
//   Phase A: total = sum(g_count). If total == NBLK (always on this input):
//            speculative stores are the answer -> return.
//   Sparse fallback: per-CTA smem scan + bitmap ranking; each thread
//            rewrites its OWN slots (same-thread WAW, no race).
// ---------------------------------------------------------------------------
#define WT      256
#define WSLOTS  2
#define WGRID   ((OUT_VEC4 + WT*WSLOTS - 1) / (WT*WSLOTS))   // 250
#define WCHUNK  ((NROW + WT - 1) / WT)    // 10

__device__ __forceinline__ int nth_set_bit(unsigned w, int n)  // n-th (0-based)
{
    return (int)__fns(w, 0, n + 1);
}

__device__ __forceinline__ void resolve_dense(unsigned p,
                                              float& x, float& y, float& z)
{
    unsigned n = p / BC2;
    unsigned r = p - n * BC2;
    x = (float)n;
    y = (float)(r / BC);
    z = (float)(r % BC);
}

__device__ __forceinline__ void resolve_gen(unsigned p, unsigned total,
                                            const unsigned* __restrict__ s_off,
                                            float& x, float& y, float& z)
{
    if (p >= total) { x = -1.f; y = -1.f; z = -1.f; return; }

    int lo = 0, hi = NROW - 1;
    while (lo < hi) {
        int mid = (lo + hi + 1) >> 1;
        if (s_off[mid] <= p) lo = mid; else hi = mid - 1;
    }
    const int row  = lo;
    int       rank = (int)(p - s_off[row]);

    unsigned w0 = g_bitmap[row * 3 + 0];
    unsigned w1 = g_bitmap[row * 3 + 1];
    unsigned w2 = g_bitmap[row * 3 + 2];
    int c0 = __popc(w0), c1 = __popc(w1);
    int bw;
    if (rank < c0)            bw = nth_set_bit(w0, rank);
    else if (rank - c0 < c1)  bw = 32 + nth_set_bit(w1, rank - c0);
    else                      bw = 64 + nth_set_bit(w2, rank - c0 - c1);

    x = (float)(row / BC);
    y = (float)(row % BC);
    z = (float)bw;
}

__device__ __forceinline__ float4 phase_pack(int phase,
                                             float a0, float a1, float a2,
                                             float b0, float b1, float b2)
{
    if (phase == 0) return make_float4(a0, a1, a2, b0);
    if (phase == 1) return make_float4(a1, a2, b0, b1);
    return make_float4(a2, b0, b1, b2);
}

__global__ __launch_bounds__(WT) void write_kernel(float4* __restrict__ out)
{
    __shared__ unsigned s_off[NROW];          // sparse fallback only
    __shared__ unsigned s_wsum[WT / 32];
    __shared__ unsigned s_total;

    const int tid = threadIdx.x;

    // ---- Phase 0: speculative dense stores (independent of pool) ----
    #pragma unroll
    for (int k = 0; k < WSLOTS; ++k) {
        const int slot = (blockIdx.x * WSLOTS + k) * WT + tid;
        if (slot >= OUT_VEC4) continue;
        const unsigned p0 = ((unsigned)slot * 4u) / 3u;
        float a0, a1, a2, b0, b1, b2;
        resolve_dense(p0, a0, a1, a2);
        if (p0 + 1u < NBLK) resolve_dense(p0 + 1u, b0, b1, b2);
        else { b0 = -1.f; b1 = -1.f; b2 = -1.f; }
        out[slot] = phase_pack(slot % 3, a0, a1, a2, b0, b1, b2);
    }

    // ---- wait for pool's g_count/g_bitmap to be visible ----
    cudaGridDependencySynchronize();

    // ---- Phase A: total = sum(g_count) ----
    unsigned v = 0;
    #pragma unroll
    for (int k = 0; k < WCHUNK; ++k) {
        int i = k * WT + tid;
        if (i < NROW) v += g_count[i];
    }
    #pragma unroll
    for (int o = 16; o >= 1; o >>= 1)
        v += __shfl_down_sync(0xFFFFFFFFu, v, o);
    if ((tid & 31) == 0) s_wsum[tid >> 5] = v;
    __syncthreads();
    if (tid == 0) {
        unsigned t = 0;
        #pragma unroll
        for (int w = 0; w < WT / 32; ++w) t += s_wsum[w];
        s_total = t;
    }
    __syncthreads();
    const unsigned total = s_total;

    if (total == NBLK) return;                // dense: speculative stores stand

    // ---- sparse fallback: full exclusive scan into s_off ----
    for (int i = tid; i < NROW; i += WT) s_off[i] = g_count[i];
    __syncthreads();
    {
        __shared__ unsigned s_part[WT];
        const int start = tid * WCHUNK;
        const int end   = (start + WCHUNK < NROW) ? (start + WCHUNK) : NROW;
        unsigned sum = 0;
        for (int i = start; i < end; ++i) sum += s_off[i];
        s_part[tid] = sum;
        __syncthreads();
        for (int off = 1; off < WT; off <<= 1) {
            unsigned t = (tid >= off) ? s_part[tid - off] : 0u;
            __syncthreads();
            s_part[tid] += t;
            __syncthreads();
        }
        unsigned run = (tid > 0) ? s_part[tid - 1] : 0u;
        for (int i = start; i < end; ++i) {
            unsigned c = s_off[i];
            s_off[i] = run;
            run += c;
        }
        __syncthreads();
    }

    // rewrite my OWN slots with the correct sparse values
    #pragma unroll
    for (int k = 0; k < WSLOTS; ++k) {
        const int slot = (blockIdx.x * WSLOTS + k) * WT + tid;
        if (slot >= OUT_VEC4) continue;
        const unsigned p0 = ((unsigned)slot * 4u) / 3u;
        float a0, a1, a2, b0, b1, b2;
        resolve_gen(p0,      total, s_off, a0, a1, a2);
        resolve_gen(p0 + 1u, total, s_off, b0, b1, b2);
        out[slot] = phase_pack(slot % 3, a0, a1, a2, b0, b1, b2);
    }
}

// ---------------------------------------------------------------------------
extern "C" void kernel_launch(void* const* d_in, const int* in_sizes, int n_in,
                              void* d_out, int out_size)
{
    const float* mask = (const float*)d_in[0];

    pool_kernel<<<NROW, 128>>>(mask);

    // PDL: write_kernel launches while pool is still in flight; its
    // pool-independent phase overlaps pool, and it blocks at
    // cudaGridDependencySynchronize() until pool's memory is visible.
    cudaLaunchConfig_t cfg = {};
    cfg.gridDim  = dim3(WGRID, 1, 1);
    cfg.blockDim = dim3(WT, 1, 1);
    cfg.dynamicSmemBytes = 0;
    cfg.stream = 0;
    cudaLaunchAttribute attr[1];
    attr[0].id = cudaLaunchAttributeProgrammaticStreamSerialization;
    attr[0].val.programmaticStreamSerializationAllowed = 1;
    cfg.attrs = attr;
    cfg.numAttrs = 1;
    cudaLaunchKernelEx(&cfg, write_kernel, (float4*)d_out);
}

// round 15
// speedup vs baseline: 1.0025x; 1.0025x over previous
#include <cuda_runtime.h>
#include <cuda_bf16.h>

// ---- static problem config ----
#define NIMG 32
#define HH   1024
#define WW   1024
#define BHW  16                 // pool window
#define BSTR 14                 // block stride
#define BC   73                 // blocks per spatial dim
#define BC2  (BC*BC)            // 5329
#define NROW (NIMG*BC)          // 2336  (n, bh) row-blocks
#define NBLK (NROW*BC)          // 170528 total blocks
#define OUT_ELEMS (NBLK*3)      // 511584 floats = 127896 float4 (exact)
#define OUT_VEC4  (OUT_ELEMS/4)
#define THRESH 0.9f
#define W4     (WW/4)

// scratch (device globals — no allocation allowed)
__device__ unsigned g_bitmap[NROW * 3];   // 96-bit active mask per (n,bh) row
__device__ unsigned g_count[NROW];        // popcount per row

__device__ __forceinline__ float4 fmax4(float4 a, float4 b)
{
    return make_float4(fmaxf(a.x, b.x), fmaxf(a.y, b.y),
                       fmaxf(a.z, b.z), fmaxf(a.w, b.w));
}

// Horizontal checkpoint: publish column maxima, compute the 73 window maxima,
// ballot into sbm, return whether ALL windows are active. Must be called by
// all 128 threads (contains barriers); call sites are CTA-uniform.
__device__ __forceinline__ bool checkpoint(float4 a0, float4 a1,
                                           float4* __restrict__ sv4,
                                           unsigned* __restrict__ sbm, int tid)
{
    sv4[tid]       = a0;
    sv4[tid + 128] = a1;
    __syncthreads();
    const float* sv = (const float*)sv4;
    if (tid < 96) {                       // warps 0,1,2
        float m = 0.f;
        if (tid < BC) {
            const int w0 = tid * BSTR - 1;
            const int ws = (w0 < 0) ? 0 : w0;
            const int we = (w0 + BHW < WW) ? (w0 + BHW) : WW;
            for (int w = ws; w < we; ++w) m = fmaxf(m, sv[w]);
        }
        unsigned b = __ballot_sync(0xFFFFFFFFu, m > THRESH);
        if ((tid & 31) == 0) sbm[tid >> 5] = b;
    }
    __syncthreads();
    return (sbm[0] == 0xFFFFFFFFu) &
           (sbm[1] == 0xFFFFFFFFu) &
           (sbm[2] == 0x1FFu);
}

// Front-batched 4-row chunk: 8 independent float4 loads, folded into a0/a1.
__device__ __forceinline__ void load4rows(const float4* __restrict__ base,
                                          int r0, int tid,
                                          float4& a0, float4& a1)
{
    float4 x0 = base[(r0 + 0) * W4 + tid];
    float4 y0 = base[(r0 + 0) * W4 + 128 + tid];
    float4 x1 = base[(r0 + 1) * W4 + tid];
    float4 y1 = base[(r0 + 1) * W4 + 128 + tid];
    float4 x2 = base[(r0 + 2) * W4 + tid];
    float4 y2 = base[(r0 + 2) * W4 + 128 + tid];
    float4 x3 = base[(r0 + 3) * W4 + tid];
    float4 y3 = base[(r0 + 3) * W4 + 128 + tid];
    a0 = fmax4(a0, fmax4(fmax4(x0, x1), fmax4(x2, x3)));
    a1 = fmax4(a1, fmax4(fmax4(y0, y1), fmax4(y2, y3)));
}

// ---------------------------------------------------------------------------
// K1: pool. One CTA per (n, bh), 128 threads (2 float4 columns each).
// MONOTONE EARLY EXIT, now with THREE checkpoints:
//   chunk 1 = rows 0-3   -> ~92% of CTAs exit    (P(window undecided)=0.9^64)
//   chunk 2 = rows 4-7   -> ~99.99% exit          (0.9^128 per window)
//   chunk 3 = rows 8-end -> the ~1e-4 remainder
// Expected rows/CTA ~= 4.33 (was 4.99 with one checkpoint), and straggler
// critical path is a 4-row chain instead of 12. Correct for any input; zero
// is the exact identity (zero padding, mask in [0,1)).
// ---------------------------------------------------------------------------
__global__ __launch_bounds__(128) void pool_kernel(const float* __restrict__ mask)
{
    const int cta = blockIdx.x;          // n*BC + bh
    const int n   = cta / BC;
    const int bh  = cta % BC;
    const int tid = threadIdx.x;

    __shared__ float4   sv4[256];        // 1024 column maxima
    __shared__ unsigned sbm[3];

    // padded window [bh*14, bh*14+16) -> unpadded rows [bh*14-1, bh*14+15)
    const int h0 = bh * BSTR - 1;
    const int hs = (h0 < 0) ? 0 : h0;
    const int he = (h0 + BHW < HH) ? (h0 + BHW) : HH;
    const int total_rows = he - hs;      // 15 (bh==0) or 16

    const float4* base = (const float4*)(mask + (size_t)n * HH * WW) + hs * W4;

    float4 a0 = make_float4(0.f, 0.f, 0.f, 0.f);
    float4 a1 = make_float4(0.f, 0.f, 0.f, 0.f);

    // ---- chunk 1: rows 0-3 ----
    load4rows(base, 0, tid, a0, a1);
    bool done = checkpoint(a0, a1, sv4, sbm, tid);

    if (!done) {
        // ---- chunk 2: rows 4-7 ----
        load4rows(base, 4, tid, a0, a1);
        done = checkpoint(a0, a1, sv4, sbm, tid);

        if (!done) {
            // ---- chunk 3: rows 8..total_rows-1 (7 or 8 rows) ----
            #pragma unroll 4
            for (int h = 8; h < total_rows; ++h) {
                a0 = fmax4(a0, base[h * W4 + tid]);
                a1 = fmax4(a1, base[h * W4 + 128 + tid]);
            }
            (void)checkpoint(a0, a1, sv4, sbm, tid);
        }
    }

    if (tid < 3) g_bitmap[cta * 3 + tid] = sbm[tid];
    if (tid == 0)
        g_count[cta] = (unsigned)(__popc(sbm[0]) + __popc(sbm[1]) + __popc(sbm[2]));
}

// ---------------------------------------------------------------------------
// K2: write (exact R10/R12 structure — 2.7us wall, plain launch).
// Phase A: SUM of the 2336 counts -> total. Dense path (total == NBLK):
// pure divmod. Sparse fallback: smem scan + bitmap ranking (never taken).
// Phase B: 2 float4 slots per thread, register-triple phase branch.
// ---------------------------------------------------------------------------
#define WT      256
#define WSLOTS  2
#define WGRID   ((OUT_VEC4 + WT*WSLOTS - 1) / (WT*WSLOTS))   // 250
#define WCHUNK  ((NROW + WT - 1) / WT)    // 10

__device__ __forceinline__ int nth_set_bit(unsigned w, int n)  // n-th (0-based)
{
    return (int)__fns(w, 0, n + 1);
}

__device__ __forceinline__ void resolve_dense(unsigned p,
                                              float& x, float& y, float& z)
{
    unsigned n = p / BC2;
    unsigned r = p - n * BC2;
    x = (float)n;
    y = (float)(r / BC);
    z = (float)(r % BC);
}

__device__ __forceinline__ void resolve_gen(unsigned p, unsigned total,
                                            const unsigned* __restrict__ s_off,
                                            float& x, float& y, float& z)
{
    if (p >= total) { x = -1.f; y = -1.f; z = -1.f; return; }

    int lo = 0, hi = NROW - 1;
    while (lo < hi) {
        int mid = (lo + hi + 1) >> 1;
        if (s_off[mid] <= p) lo = mid; else hi = mid - 1;
    }
    const int row  = lo;
    int       rank = (int)(p - s_off[row]);

    unsigned w0 = g_bitmap[row * 3 + 0];
    unsigned w1 = g_bitmap[row * 3 + 1];
    unsigned w2 = g_bitmap[row * 3 + 2];
    int c0 = __popc(w0), c1 = __popc(w1);
    int bw;
    if (rank < c0)            bw = nth_set_bit(w0, rank);
    else if (rank - c0 < c1)  bw = 32 + nth_set_bit(w1, rank - c0);
    else                      bw = 64 + nth_set_bit(w2, rank - c0 - c1);

    x = (float)(row / BC);
    y = (float)(row % BC);
    z = (float)bw;
}

__device__ __forceinline__ float4 phase_pack(int phase,
                                             float a0, float a1, float a2,
                                             float b0, float b1, float b2)
{
    if (phase == 0) return make_float4(a0, a1, a2, b0);
    if (phase == 1) return make_float4(a1, a2, b0, b1);
    return make_float4(a2, b0, b1, b2);
}

__global__ __launch_bounds__(WT) void write_kernel(float4* __restrict__ out)
{
    __shared__ unsigned s_off[NROW];          // sparse fallback only
    __shared__ unsigned s_wsum[WT / 32];
    __shared__ unsigned s_total;

    const int tid = threadIdx.x;

    // ---- Phase A: total = sum(g_count) ----
    unsigned v = 0;
    #pragma unroll
    for (int k = 0; k < WCHUNK; ++k) {
        int i = k * WT + tid;
        if (i < NROW) v += g_count[i];
    }
    #pragma unroll
    for (int o = 16; o >= 1; o >>= 1)
        v += __shfl_down_sync(0xFFFFFFFFu, v, o);
    if ((tid & 31) == 0) s_wsum[tid >> 5] = v;
    __syncthreads();
    if (tid == 0) {
        unsigned t = 0;
        #pragma unroll
        for (int w = 0; w < WT / 32; ++w) t += s_wsum[w];
        s_total = t;
    }
    __syncthreads();
    const unsigned total = s_total;

    const bool dense = (total == NBLK);
    if (!dense) {
        // ---- sparse fallback: full exclusive scan into s_off ----
        for (int i = tid; i < NROW; i += WT) s_off[i] = g_count[i];
        __syncthreads();
        __shared__ unsigned s_part[WT];
        const int start = tid * WCHUNK;
        const int end   = (start + WCHUNK < NROW) ? (start + WCHUNK) : NROW;
        unsigned sum = 0;
        for (int i = start; i < end; ++i) sum += s_off[i];
        s_part[tid] = sum;
        __syncthreads();
        for (int off = 1; off < WT; off <<= 1) {
            unsigned t = (tid >= off) ? s_part[tid - off] : 0u;
            __syncthreads();
            s_part[tid] += t;
            __syncthreads();
        }
        unsigned run = (tid > 0) ? s_part[tid - 1] : 0u;
        for (int i = start; i < end; ++i) {
            unsigned c = s_off[i];
            s_off[i] = run;
            run += c;
        }
        __syncthreads();
    }

    // ---- Phase B: WSLOTS float4 slots per thread ----
    #pragma unroll
    for (int k = 0; k < WSLOTS; ++k) {
        const int slot = (blockIdx.x * WSLOTS + k) * WT + tid;
        if (slot >= OUT_VEC4) continue;

        const unsigned p0 = ((unsigned)slot * 4u) / 3u;
        float a0, a1, a2, b0, b1, b2;
        if (dense) {
            resolve_dense(p0, a0, a1, a2);
            if (p0 + 1u < NBLK) resolve_dense(p0 + 1u, b0, b1, b2);
            else { b0 = -1.f; b1 = -1.f; b2 = -1.f; }
        } else {
            resolve_gen(p0,      total, s_off, a0, a1, a2);
            resolve_gen(p0 + 1u, total, s_off, b0, b1, b2);
        }

        out[slot] = phase_pack(slot % 3, a0, a1, a2, b0, b1, b2);
    }
}

// ---------------------------------------------------------------------------
extern "C" void kernel_launch(void* const* d_in, const int* in_sizes, int n_in,
                              void* d_out, int out_size)
{
    const float* mask = (const float*)d_in[0];

    pool_kernel<<<NROW, 128>>>(mask);
    write_kernel<<<WGRID, WT>>>((float4*)d_out);
}

// round 16
// speedup vs baseline: 1.0226x; 1.0201x over previous
#include <cuda_runtime.h>
#include <cuda_bf16.h>

// ---- static problem config ----
#define NIMG 32
#define HH   1024
#define WW   1024
#define BHW  16                 // pool window
#define BSTR 14                 // block stride
#define BC   73                 // blocks per spatial dim
#define BC2  (BC*BC)            // 5329
#define NROW (NIMG*BC)          // 2336  (n, bh) row-blocks
#define NBLK (NROW*BC)          // 170528 total blocks
#define OUT_ELEMS (NBLK*3)      // 511584 floats = 127896 float4 (exact)
#define OUT_VEC4  (OUT_ELEMS/4)
#define THRESH 0.9f
#define W4     (WW/4)

// scratch (device globals — no allocation allowed; zero-initialized)
__device__ unsigned g_bitmap[NROW * 3];     // 96-bit active mask per (n,bh) row
__device__ unsigned g_count[NROW];          // popcount per row
__device__ unsigned g_offset[NROW];         // sparse fallback scan (cold)
__device__ unsigned long long g_state;      // (done_ctas << 32) | acc_count

__device__ __forceinline__ float4 fmax4(float4 a, float4 b)
{
    return make_float4(fmaxf(a.x, b.x), fmaxf(a.y, b.y),
                       fmaxf(a.z, b.z), fmaxf(a.w, b.w));
}

__device__ __forceinline__ int nth_set_bit(unsigned w, int n)  // n-th (0-based)
{
    return (int)__fns(w, 0, n + 1);
}

__device__ __forceinline__ void resolve_dense(unsigned p,
                                              float& x, float& y, float& z)
{
    unsigned n = p / BC2;
    unsigned r = p - n * BC2;
    x = (float)n;
    y = (float)(r / BC);
    z = (float)(r % BC);
}

__device__ __forceinline__ float4 phase_pack(int phase,
                                             float a0, float a1, float a2,
                                             float b0, float b1, float b2)
{
    if (phase == 0) return make_float4(a0, a1, a2, b0);
    if (phase == 1) return make_float4(a1, a2, b0, b1);
    return make_float4(a2, b0, b1, b2);
}

// Horizontal checkpoint: publish column maxima, compute 73 window maxima,
// ballot into sbm, return whether ALL windows are active. All 128 threads.
__device__ __forceinline__ bool checkpoint(float4 a0, float4 a1,
                                           float4* __restrict__ sv4,
                                           unsigned* __restrict__ sbm, int tid)
{
    sv4[tid]       = a0;
    sv4[tid + 128] = a1;
    __syncthreads();
    const float* sv = (const float*)sv4;
    if (tid < 96) {                       // warps 0,1,2
        float m = 0.f;
        if (tid < BC) {
            const int w0 = tid * BSTR - 1;
            const int ws = (w0 < 0) ? 0 : w0;
            const int we = (w0 + BHW < WW) ? (w0 + BHW) : WW;
            for (int w = ws; w < we; ++w) m = fmaxf(m, sv[w]);
        }
        unsigned b = __ballot_sync(0xFFFFFFFFu, m > THRESH);
        if ((tid & 31) == 0) sbm[tid >> 5] = b;
    }
    __syncthreads();
    return (sbm[0] == 0xFFFFFFFFu) &
           (sbm[1] == 0xFFFFFFFFu) &
           (sbm[2] == 0x1FFu);
}

// COLD sparse fallback: the last CTA rewrites the entire output. Scans the
// 2336 counts (partials in smem, offsets in g_offset), then grid-strides all
// output slots with binary search + bitmap bit-ranking. Never taken on the
// bench input; kept for correctness on arbitrary inputs.
__device__ __noinline__ void sparse_rewrite(float4* __restrict__ out,
                                            unsigned total, int tid)
{
    __shared__ unsigned s_part[128];
    const int CH = (NROW + 127) / 128;   // 19

    const int start = tid * CH;
    const int end   = (start + CH < NROW) ? (start + CH) : NROW;
    unsigned sum = 0;
    for (int i = start; i < end; ++i) sum += g_count[i];
    s_part[tid] = sum;
    __syncthreads();
    for (int off = 1; off < 128; off <<= 1) {
        unsigned t = (tid >= off) ? s_part[tid - off] : 0u;
        __syncthreads();
        s_part[tid] += t;
        __syncthreads();
    }
    unsigned run = (tid > 0) ? s_part[tid - 1] : 0u;
    for (int i = start; i < end; ++i) {
        unsigned c = g_count[i];
        g_offset[i] = run;
        run += c;
    }
    __syncthreads();

    for (int slot = tid; slot < OUT_VEC4; slot += 128) {
        const unsigned p0 = ((unsigned)slot * 4u) / 3u;
        float t[6];
        #pragma unroll
        for (int q = 0; q < 2; ++q) {
            unsigned p = p0 + (unsigned)q;
            float* x = &t[3 * q];
            if (p >= total) { x[0] = -1.f; x[1] = -1.f; x[2] = -1.f; continue; }
            int lo = 0, hi = NROW - 1;
            while (lo < hi) {
                int mid = (lo + hi + 1) >> 1;
                if (g_offset[mid] <= p) lo = mid; else hi = mid - 1;
            }
            int rank = (int)(p - g_offset[lo]);
            unsigned w0 = g_bitmap[lo * 3 + 0];
            unsigned w1 = g_bitmap[lo * 3 + 1];
            unsigned w2 = g_bitmap[lo * 3 + 2];
            int c0 = __popc(w0), c1 = __popc(w1);
            int bw;
            if (rank < c0)            bw = nth_set_bit(w0, rank);
            else if (rank - c0 < c1)  bw = 32 + nth_set_bit(w1, rank - c0);
            else                      bw = 64 + nth_set_bit(w2, rank - c0 - c1);
            x[0] = (float)(lo / BC);
            x[1] = (float)(lo % BC);
            x[2] = (float)bw;
        }
        out[slot] = phase_pack(slot % 3, t[0], t[1], t[2], t[3], t[4], t[5]);
    }
}

// ---------------------------------------------------------------------------
// Single fused kernel. One CTA per (n, bh), 128 threads (2 float4 cols each).
//  1. Issue the 8 chunk-1 loads FIRST (critical path).
//  2. Speculative dense output store in the load shadow — the dense result
//     (total == NBLK, always true for this input) is a pure function of the
//     slot index, independent of pooling.
//  3. Checkpoint (monotone early exit, ~92% stop at 4 rows); survivors read
//     the remaining rows and re-checkpoint.
//  4. Tail: tid0 publishes bitmap+count, ONE fence, ONE packed 64-bit atomic
//     ((1<<32)+count). Last-arriving CTA: total == NBLK -> reset state,
//     return (speculative output stands). Else cold sparse rewrite.
// smem = 4.1 KB -> 16 CTAs/SM (sparse scratch lives in g_offset, not smem).
// ---------------------------------------------------------------------------
__global__ __launch_bounds__(128) void fused_kernel(const float* __restrict__ mask,
                                                    float4* __restrict__ out)
{
    const int cta = blockIdx.x;          // n*BC + bh
    const int n   = cta / BC;
    const int bh  = cta % BC;
    const int tid = threadIdx.x;

    __shared__ float4   sv4[256];        // 1024 column maxima
    __shared__ unsigned sbm[3];
    __shared__ unsigned s_total;
    __shared__ bool     s_last;

    // padded window [bh*14, bh*14+16) -> unpadded rows [bh*14-1, bh*14+15)
    const int h0 = bh * BSTR - 1;
    const int hs = (h0 < 0) ? 0 : h0;
    const int he = (h0 + BHW < HH) ? (h0 + BHW) : HH;
    const int total_rows = he - hs;      // 15 (bh==0) or 16

    const float4* base = (const float4*)(mask + (size_t)n * HH * WW) + hs * W4;

    // ---- 1. chunk-1 loads first: 8 independent LDG.128 ----
    float4 x0 = base[0 * W4 + tid];
    float4 y0 = base[0 * W4 + 128 + tid];
    float4 x1 = base[1 * W4 + tid];
    float4 y1 = base[1 * W4 + 128 + tid];
    float4 x2 = base[2 * W4 + tid];
    float4 y2 = base[2 * W4 + 128 + tid];
    float4 x3 = base[3 * W4 + tid];
    float4 y3 = base[3 * W4 + 128 + tid];

    // ---- 2. speculative dense store (ALU hides in the load shadow) ----
    {
        const int slot = cta * 128 + tid;
        if (slot < OUT_VEC4) {
            const unsigned p0 = ((unsigned)slot * 4u) / 3u;
            float a0, a1, a2, b0, b1, b2;
            resolve_dense(p0, a0, a1, a2);
            if (p0 + 1u < NBLK) resolve_dense(p0 + 1u, b0, b1, b2);
            else { b0 = -1.f; b1 = -1.f; b2 = -1.f; }
            out[slot] = phase_pack(slot % 3, a0, a1, a2, b0, b1, b2);
        }
    }

    // ---- 3. reduce + checkpoint (monotone early exit) ----
    float4 a0 = fmax4(fmax4(x0, x1), fmax4(x2, x3));
    float4 a1 = fmax4(fmax4(y0, y1), fmax4(y2, y3));
    bool done = checkpoint(a0, a1, sv4, sbm, tid);

    if (!done) {
        #pragma unroll 4
        for (int h = 4; h < total_rows; ++h) {
            a0 = fmax4(a0, base[h * W4 + tid]);
            a1 = fmax4(a1, base[h * W4 + 128 + tid]);
        }
        (void)checkpoint(a0, a1, sv4, sbm, tid);
    }

    // ---- 4. publish + packed-atomic completion tail ----
    if (tid == 0) {
        const unsigned c = (unsigned)(__popc(sbm[0]) + __popc(sbm[1]) + __popc(sbm[2]));
        g_bitmap[cta * 3 + 0] = sbm[0];
        g_bitmap[cta * 3 + 1] = sbm[1];
        g_bitmap[cta * 3 + 2] = sbm[2];
        g_count[cta] = c;
        __threadfence();                  // publish before signaling
        unsigned long long prev =
            atomicAdd(&g_state, (1ULL << 32) + (unsigned long long)c);
        const unsigned done_ctas = (unsigned)(prev >> 32);
        s_last  = (done_ctas == (unsigned)(NROW - 1));
        s_total = (unsigned)(prev & 0xFFFFFFFFull) + c;
    }
    __syncthreads();
    if (!s_last) return;

    if (tid == 0) g_state = 0;           // reset for next graph replay

    if (s_total == NBLK) return;         // dense: speculative output correct

    __threadfence();                     // acquire side before reading peers
    sparse_rewrite(out, s_total, tid);   // cold; never on this input
}

// ---------------------------------------------------------------------------
extern "C" void kernel_launch(void* const* d_in, const int* in_sizes, int n_in,
                              void* d_out, int out_size)
{
    const float* mask = (const float*)d_in[0];

    fused_kernel<<<NROW, 128>>>(mask, (float4*)d_out);
}